// round 16
// baseline (speedup 1.0000x reference)
#include <cuda_runtime.h>

// Find_Ring_Bonds: B=16384 molecules, A=80 atoms, D=4 neighbors, R=10 rings, S=8.
// edges: [B, A, D] float32 (integer-valued, -1 = null neighbor)
// rings: [B, R, S] int32 (-1 = padding)
// out:   [B, A, D] float32 (1.0 iff bond (a, e[a][d]) lies in some ring)
//
// Warp-private version. R15 showed four structurally different kernels all
// pinned at 10.7us with every pipe at 30-46% -> the block-wide barrier
// lockstep serializes LSU work against DRAM latency. Here ONE WARP owns one
// molecule with private shared scratch; phases are separated by __syncwarp()
// only, so warps pipeline independently and LSU/DRAM/issue overlap.
//
// Ring membership via the R12 RMW-free byte scatter: 16-byte staging row per
// atom, flag byte per ring, plain byte STS (per-lane byte enables, no RMW
// hazard), collapsed to a 10-bit mask by movemask multiplies (ring bit order
// permuted but consistent; masks only ever ANDed against each other).

static constexpr int A = 80;
static constexpr int D = 4;
static constexpr int R = 10;
static constexpr int S = 8;
static constexpr int WARPS_PER_BLOCK = 8;
static constexpr int THREADS = WARPS_PER_BLOCK * 32;   // 256

__global__ __launch_bounds__(THREADS, 8)
void find_ring_bonds_kernel(const float* __restrict__ edges,
                            const int*   __restrict__ rings,
                            float*       __restrict__ out,
                            int batch)
{
    __shared__ uint4        staging[WARPS_PER_BLOCK][A];   // 16 flag bytes/atom
    __shared__ unsigned int masks[WARPS_PER_BLOCK][A];

    const int w    = threadIdx.x >> 5;     // warp in block -> molecule owner
    const int lane = threadIdx.x & 31;
    const int mol  = blockIdx.x * WARPS_PER_BLOCK + w;
    if (mol >= batch) return;              // warp-uniform exit

    const float4* E = reinterpret_cast<const float4*>(edges) + (long)mol * A;
    const int4*   Rv = reinterpret_cast<const int4*>(rings) + (long)mol * (R * S / 4);

    // ---- Front-batch all global loads for this molecule (MLP up to 4/lane).
    const float4 ea0 = E[lane];                       // atoms 0..31
    const float4 ea1 = E[32 + lane];                  // atoms 32..63
    float4 ea2 = make_float4(-1.f, -1.f, -1.f, -1.f); // atoms 64..79
    if (lane < A - 64) ea2 = E[64 + lane];
    int4 rv = make_int4(-1, -1, -1, -1);
    if (lane < (R * S / 4)) rv = Rv[lane];            // 4 ring entries / lane

    // ---- Zero staging rows (one STS.128 per owned atom).
    const uint4 z = make_uint4(0u, 0u, 0u, 0u);
    staging[w][lane]      = z;
    staging[w][32 + lane] = z;
    if (lane < A - 64) staging[w][64 + lane] = z;
    __syncwarp();

    // ---- RMW-free byte scatter: lane l owns ring entries 4l..4l+3.
    if (lane < (R * S / 4)) {
        const int base = lane * 4;
        const int v0 = rv.x, v1 = rv.y, v2 = rv.z, v3 = rv.w;
        if (v0 >= 0) reinterpret_cast<char*>(&staging[w][v0])[(base + 0) >> 3] = 1;
        if (v1 >= 0) reinterpret_cast<char*>(&staging[w][v1])[(base + 1) >> 3] = 1;
        if (v2 >= 0) reinterpret_cast<char*>(&staging[w][v2])[(base + 2) >> 3] = 1;
        if (v3 >= 0) reinterpret_cast<char*>(&staging[w][v3])[(base + 3) >> 3] = 1;
    }
    __syncwarp();

    // ---- Collapse staging rows into 10-bit masks (movemask multiplies).
    const unsigned int M = 0x08040201u;
    unsigned int mk0, mk1, mk2 = 0u;
    {
        const uint4 r0 = staging[w][lane];
        mk0 = ((r0.x * M) >> 24 & 0xFu) | (((r0.y * M) >> 24 & 0xFu) << 4)
            | (((r0.z * M) >> 24 & 0xFu) << 8);
        masks[w][lane] = mk0;

        const uint4 r1 = staging[w][32 + lane];
        mk1 = ((r1.x * M) >> 24 & 0xFu) | (((r1.y * M) >> 24 & 0xFu) << 4)
            | (((r1.z * M) >> 24 & 0xFu) << 8);
        masks[w][32 + lane] = mk1;

        if (lane < A - 64) {
            const uint4 r2 = staging[w][64 + lane];
            mk2 = ((r2.x * M) >> 24 & 0xFu) | (((r2.y * M) >> 24 & 0xFu) << 4)
                | (((r2.z * M) >> 24 & 0xFu) << 8);
            masks[w][64 + lane] = mk2;
        }
    }
    __syncwarp();

    // ---- Resolve neighbor slots and store.
    float4* O = reinterpret_cast<float4*>(out) + (long)mol * A;

    {
        const int e0 = (int)ea0.x, e1 = (int)ea0.y, e2 = (int)ea0.z, e3 = (int)ea0.w;
        float4 o;
        o.x = (e0 >= 0 && (mk0 & masks[w][e0])) ? 1.0f : 0.0f;
        o.y = (e1 >= 0 && (mk0 & masks[w][e1])) ? 1.0f : 0.0f;
        o.z = (e2 >= 0 && (mk0 & masks[w][e2])) ? 1.0f : 0.0f;
        o.w = (e3 >= 0 && (mk0 & masks[w][e3])) ? 1.0f : 0.0f;
        O[lane] = o;
    }
    {
        const int e0 = (int)ea1.x, e1 = (int)ea1.y, e2 = (int)ea1.z, e3 = (int)ea1.w;
        float4 o;
        o.x = (e0 >= 0 && (mk1 & masks[w][e0])) ? 1.0f : 0.0f;
        o.y = (e1 >= 0 && (mk1 & masks[w][e1])) ? 1.0f : 0.0f;
        o.z = (e2 >= 0 && (mk1 & masks[w][e2])) ? 1.0f : 0.0f;
        o.w = (e3 >= 0 && (mk1 & masks[w][e3])) ? 1.0f : 0.0f;
        O[32 + lane] = o;
    }
    if (lane < A - 64) {
        const int e0 = (int)ea2.x, e1 = (int)ea2.y, e2 = (int)ea2.z, e3 = (int)ea2.w;
        float4 o;
        o.x = (e0 >= 0 && (mk2 & masks[w][e0])) ? 1.0f : 0.0f;
        o.y = (e1 >= 0 && (mk2 & masks[w][e1])) ? 1.0f : 0.0f;
        o.z = (e2 >= 0 && (mk2 & masks[w][e2])) ? 1.0f : 0.0f;
        o.w = (e3 >= 0 && (mk2 & masks[w][e3])) ? 1.0f : 0.0f;
        O[64 + lane] = o;
    }
}

extern "C" void kernel_launch(void* const* d_in, const int* in_sizes, int n_in,
                              void* d_out, int out_size)
{
    const float* edges = (const float*)d_in[0];   // [B, A, D] float32
    const int*   rings = (const int*)d_in[1];     // [B, R, S] int32
    float* out = (float*)d_out;                   // [B, A, D, 1] float32

    const int batch = out_size / (A * D);                            // 16384
    const int grid = (batch + WARPS_PER_BLOCK - 1) / WARPS_PER_BLOCK; // 2048

    find_ring_bonds_kernel<<<grid, THREADS>>>(edges, rings, out, batch);
}